// round 6
// baseline (speedup 1.0000x reference)
#include <cuda_runtime.h>

#define B_ 32
#define Q_ 16
#define K_ 4096
#define D_ 128
#define V_ 128
#define THREADS 128        /* 4 warps per block */
#define NWARP 4
#define GRID 512           /* 2048 warps x 64 keys */
#define KW 64              /* keys per warp */
#define CHUNK 32           /* keys per chunk */
#define ATP 20             /* padded att row (floats), 16B-aligned */
#define SCALE 0.08838834764831845f  /* 1/sqrt(128) */

typedef unsigned long long u64;

// scratch for attn if harness only validates `output`
__device__ float g_attn_scratch[(size_t)B_ * Q_ * K_];

__device__ __forceinline__ void red_add_v4(float* p, float4 v) {
    asm volatile("red.global.add.v4.f32 [%0], {%1,%2,%3,%4};"
                 :: "l"(p), "f"(v.x), "f"(v.y), "f"(v.z), "f"(v.w) : "memory");
}
__device__ __forceinline__ void cp_async16(void* smem_dst, const void* gsrc) {
    unsigned s = (unsigned)__cvta_generic_to_shared(smem_dst);
    asm volatile("cp.async.cg.shared.global [%0], [%1], 16;" :: "r"(s), "l"(gsrc));
}
__device__ __forceinline__ void cp_async_commit() { asm volatile("cp.async.commit_group;"); }
__device__ __forceinline__ void cp_async_wait_all() { asm volatile("cp.async.wait_group 0;"); }

__device__ __forceinline__ void ffma2(u64& acc, u64 a, u64 b) {
    asm("fma.rn.f32x2 %0, %1, %2, %0;" : "+l"(acc) : "l"(a), "l"(b));
}
__device__ __forceinline__ u64 mul2(u64 a, u64 b) {
    u64 r; asm("mul.rn.f32x2 %0, %1, %2;" : "=l"(r) : "l"(a), "l"(b)); return r;
}
__device__ __forceinline__ u64 add2(u64 a, u64 b) {
    u64 r; asm("add.rn.f32x2 %0, %1, %2;" : "=l"(r) : "l"(a), "l"(b)); return r;
}
__device__ __forceinline__ u64 pack2(float x, float y) {
    u64 r; asm("mov.b64 %0, {%1,%2};" : "=l"(r) : "f"(x), "f"(y)); return r;
}
__device__ __forceinline__ void unpack2(u64 v, float& x, float& y) {
    asm("mov.b64 {%0,%1}, %2;" : "=f"(x), "=f"(y) : "l"(v));
}

__global__ __launch_bounds__(THREADS, 4)
void inv_attn_kernel(const float4* __restrict__ query4,
                     const float4* __restrict__ key4,
                     const float4* __restrict__ value4,
                     float* __restrict__ out,       // [B,Q,V] pre-zeroed, RED-accumulated
                     float* __restrict__ attn_out)  // [B,Q,K]
{
    __shared__ float  att_t[NWARP][CHUNK][ATP];  // key-major attn, 10 KB
    __shared__ float4 vt[NWARP][16][V_ / 4];     // 32 KB value staging

    const int warp = threadIdx.x >> 5;
    const int lane = threadIdx.x & 31;
    const int sub  = lane & 7;     // position within 8-lane group
    const int grp  = lane >> 3;    // 0..3
    const int gw   = blockIdx.x * NWARP + warp;   // 0..2047
    const int b    = gw >> 6;                     // 64 warps per batch
    const int kbase = (gw & 63) * KW;

    const u64 SC2 = pack2(SCALE, SCALE);

    u64 acc2[8][4];   // acc2[qp][d] = {out[2qp][lane*4+d], out[2qp+1][lane*4+d]}
    #pragma unroll
    for (int qp = 0; qp < 8; qp++)
        #pragma unroll
        for (int d = 0; d < 4; d++) acc2[qp][d] = 0ull;

    #pragma unroll 1
    for (int c = 0; c < KW / CHUNK; c++) {
        const int k0 = kbase + c * CHUNK;
        const float4* vp = value4 + ((size_t)b * K_ + k0) * (V_ / 4) + lane;

        // prefetch value rows 0-15 (lands under ph1)
        #pragma unroll
        for (int r = 0; r < 16; r++)
            cp_async16(&vt[warp][r][lane], vp + r * 32);
        cp_async_commit();

        // ---- phase 1: logits; 4 keys per LDG, 16 dims per lane ----
        #pragma unroll 1
        for (int q = 0; q < Q_; q++) {
            const ulonglong2* qp2 =
                reinterpret_cast<const ulonglong2*>(query4)
                + ((size_t)(b * Q_ + q)) * 32 + sub;
            u64 qf01[4], qf23[4];
            #pragma unroll
            for (int j = 0; j < 4; j++) {
                ulonglong2 t = __ldg(qp2 + j * 8);      // L1-resident
                qf01[j] = mul2(t.x, SC2);
                qf23[j] = mul2(t.y, SC2);
            }
            // key row for (kq,grp): k0 + kq*4 + grp ; lane float4 off = j*8+sub
            const ulonglong2* kp2 =
                reinterpret_cast<const ulonglong2*>(key4)
                + ((size_t)(b * Q_ + q) * K_ + k0 + grp) * 32 + sub;
            #pragma unroll 4
            for (int kq = 0; kq < 8; kq++) {
                u64 p01 = 0ull, p23 = 0ull;
                #pragma unroll
                for (int j = 0; j < 4; j++) {
                    ulonglong2 kv = __ldcs(kp2 + kq * 128 + j * 8);
                    ffma2(p01, qf01[j], kv.x);
                    ffma2(p23, qf23[j], kv.y);
                }
                u64 ps = add2(p01, p23);
                float plo, phi; unpack2(ps, plo, phi);
                float p = plo + phi;
                p += __shfl_xor_sync(0xffffffffu, p, 1);
                p += __shfl_xor_sync(0xffffffffu, p, 2);
                p += __shfl_xor_sync(0xffffffffu, p, 4);
                if (sub == 0) att_t[warp][kq * 4 + grp][q] = p;
            }
        }
        __syncwarp();

        // ---- phase 2: softmax over q; lane owns key k0+lane ----
        {
            const float4* ar = reinterpret_cast<const float4*>(att_t[warp][lane]);
            float l[Q_];
            #pragma unroll
            for (int i = 0; i < 4; i++)
                *reinterpret_cast<float4*>(&l[i * 4]) = ar[i];
            float mx = -1e30f;
            #pragma unroll
            for (int q = 0; q < Q_; q++) mx = fmaxf(mx, l[q]);
            float s = 0.0f;
            #pragma unroll
            for (int q = 0; q < Q_; q++) { l[q] = __expf(l[q] - mx); s += l[q]; }
            float inv = 1.0f / s;
            #pragma unroll
            for (int q = 0; q < Q_; q++) l[q] *= inv;
            float4* aw = reinterpret_cast<float4*>(att_t[warp][lane]);
            #pragma unroll
            for (int i = 0; i < 4; i++)
                aw[i] = *reinterpret_cast<float4*>(&l[i * 4]);
            #pragma unroll
            for (int q = 0; q < Q_; q++)
                __stcs(&attn_out[(size_t)(b * Q_ + q) * K_ + k0 + lane], l[q]);
        }
        __syncwarp();

        // ---- phase 3a: value rows 0-15 ----
        cp_async_wait_all();
        __syncwarp();
        #pragma unroll 4
        for (int kk = 0; kk < 16; kk++) {
            float4 vv = vt[warp][kk][lane];
            u64 vb0 = pack2(vv.x, vv.x), vb1 = pack2(vv.y, vv.y);
            u64 vb2 = pack2(vv.z, vv.z), vb3 = pack2(vv.w, vv.w);
            const u64* ap = reinterpret_cast<const u64*>(att_t[warp][kk]);
            #pragma unroll
            for (int qp = 0; qp < 8; qp++) {
                u64 a = ap[qp];                     // LDS.64 broadcast
                ffma2(acc2[qp][0], a, vb0);
                ffma2(acc2[qp][1], a, vb1);
                ffma2(acc2[qp][2], a, vb2);
                ffma2(acc2[qp][3], a, vb3);
            }
        }
        __syncwarp();

        // ---- phase 3b: value rows 16-31 ----
        #pragma unroll
        for (int r = 0; r < 16; r++)
            cp_async16(&vt[warp][r][lane], vp + (16 + r) * 32);
        cp_async_commit();
        cp_async_wait_all();
        __syncwarp();
        #pragma unroll 4
        for (int kk = 0; kk < 16; kk++) {
            float4 vv = vt[warp][kk][lane];
            u64 vb0 = pack2(vv.x, vv.x), vb1 = pack2(vv.y, vv.y);
            u64 vb2 = pack2(vv.z, vv.z), vb3 = pack2(vv.w, vv.w);
            const u64* ap = reinterpret_cast<const u64*>(att_t[warp][kk + 16]);
            #pragma unroll
            for (int qp = 0; qp < 8; qp++) {
                u64 a = ap[qp];
                ffma2(acc2[qp][0], a, vb0);
                ffma2(acc2[qp][1], a, vb1);
                ffma2(acc2[qp][2], a, vb2);
                ffma2(acc2[qp][3], a, vb3);
            }
        }
        __syncwarp();
    }

    // ---- flush: rebuild float4 per q, one RED.v4 each ----
    float* o = out + (size_t)b * Q_ * V_ + lane * 4;
    #pragma unroll
    for (int qp = 0; qp < 8; qp++) {
        float a0, b0, a1, b1, a2, b2, a3, b3;
        unpack2(acc2[qp][0], a0, b0);
        unpack2(acc2[qp][1], a1, b1);
        unpack2(acc2[qp][2], a2, b2);
        unpack2(acc2[qp][3], a3, b3);
        red_add_v4(o + (size_t)(2 * qp) * V_,     make_float4(a0, a1, a2, a3));
        red_add_v4(o + (size_t)(2 * qp + 1) * V_, make_float4(b0, b1, b2, b3));
    }
}

extern "C" void kernel_launch(void* const* d_in, const int* in_sizes, int n_in,
                              void* d_out, int out_size)
{
    const float4* query = (const float4*)d_in[0];
    const float4* key   = (const float4*)d_in[1];
    const float4* value = (const float4*)d_in[2];

    float* out = (float*)d_out;
    float* attn;
    const int out_elems  = B_ * Q_ * V_;        // 65536
    const int attn_elems = B_ * Q_ * K_;        // 2097152

    if (out_size >= out_elems + attn_elems) {
        attn = out + out_elems;                 // (output, attn) concatenated
    } else {
        cudaGetSymbolAddress((void**)&attn, g_attn_scratch);
    }

    cudaMemsetAsync(d_out, 0, (size_t)out_elems * sizeof(float));

    inv_attn_kernel<<<GRID, THREADS>>>(query, key, value, out, attn);
}

// round 7
// speedup vs baseline: 1.1006x; 1.1006x over previous
#include <cuda_runtime.h>

#define B_ 32
#define Q_ 16
#define K_ 4096
#define D_ 128
#define V_ 128
#define THREADS 128        /* 4 warps per block */
#define NWARP 4
#define GRID 512           /* 2048 warps x 64 keys */
#define KW 64
#define CHUNK 32
#define SCALE 0.08838834764831845f  /* 1/sqrt(128) */

// scratch for attn if harness only validates `output`
__device__ float g_attn_scratch[(size_t)B_ * Q_ * K_];

__device__ __forceinline__ void red_add_v4(float* p, float4 v) {
    asm volatile("red.global.add.v4.f32 [%0], {%1,%2,%3,%4};"
                 :: "l"(p), "f"(v.x), "f"(v.y), "f"(v.z), "f"(v.w) : "memory");
}

__global__ __launch_bounds__(THREADS, 4)
void inv_attn_kernel(const float4* __restrict__ query4,
                     const float4* __restrict__ key4,
                     const float4* __restrict__ value4,
                     float* __restrict__ out,       // [B,Q,V] pre-zeroed, RED-accumulated
                     float* __restrict__ attn_out)  // [B,Q,K]
{
    __shared__ float att[NWARP][2][Q_][CHUNK];   // 16 KB, double-buffered per warp

    const int warp = threadIdx.x >> 5;
    const int lane = threadIdx.x & 31;
    const int gw   = blockIdx.x * NWARP + warp;   // 0..2047
    const int b    = gw >> 6;                     // 64 warps per batch
    const int k0   = (gw & 63) * KW;              // chunk 0 base
    const int k1   = k0 + CHUNK;                  // chunk 1 base

    float4 acc[Q_];
    #pragma unroll
    for (int q = 0; q < Q_; q++) acc[q] = make_float4(0.f, 0.f, 0.f, 0.f);

    // ================= Phase A: logits for chunk 0 =================
    #pragma unroll 1
    for (int q = 0; q < Q_; q++) {
        float4 qv = __ldg(query4 + (b * Q_ + q) * (D_ / 4) + lane);
        qv.x *= SCALE; qv.y *= SCALE; qv.z *= SCALE; qv.w *= SCALE;
        const float4* kp = key4 + ((size_t)(b * Q_ + q) * K_ + k0) * (D_ / 4);
        #pragma unroll 8
        for (int kk = 0; kk < CHUNK; kk++) {
            float4 kv = __ldcs(kp + kk * 32 + lane);     // 512B coalesced row
            float p = qv.x * kv.x + qv.y * kv.y + qv.z * kv.z + qv.w * kv.w;
            p += __shfl_xor_sync(0xffffffffu, p, 16);
            p += __shfl_xor_sync(0xffffffffu, p, 8);
            p += __shfl_xor_sync(0xffffffffu, p, 4);
            p += __shfl_xor_sync(0xffffffffu, p, 2);
            p += __shfl_xor_sync(0xffffffffu, p, 1);
            if (lane == 0) att[warp][0][q][kk] = p;
        }
    }
    __syncwarp();

    // ---- softmax over q for chunk 0; lane owns key k0+lane ----
    {
        float l[Q_];
        float mx = -1e30f;
        #pragma unroll
        for (int q = 0; q < Q_; q++) { l[q] = att[warp][0][q][lane]; mx = fmaxf(mx, l[q]); }
        float s = 0.0f;
        #pragma unroll
        for (int q = 0; q < Q_; q++) { l[q] = __expf(l[q] - mx); s += l[q]; }
        float inv = 1.0f / s;
        #pragma unroll
        for (int q = 0; q < Q_; q++) {
            float a = l[q] * inv;
            att[warp][0][q][lane] = a;
            __stcs(&attn_out[(size_t)(b * Q_ + q) * K_ + k0 + lane], a);
        }
    }
    __syncwarp();

    // ====== Phase B: fused  ph1(chunk1)  +  ph3(chunk0) ======
    // Per q-iter: value LDGs + key LDG batch issued up front; the ph3 FFMAs
    // execute inside the key-load stall shadow, keeping DRAM issue continuous.
    #pragma unroll 1
    for (int q = 0; q < Q_; q++) {
        // value rows 2q, 2q+1 of chunk 0 (consumed at end of iter)
        const float4* vp = value4 + ((size_t)b * K_ + k0 + 2 * q) * (V_ / 4) + lane;
        float4 v0 = __ldcs(vp);
        float4 v1 = __ldcs(vp + 32);

        // ph1 for chunk 1, query q
        float4 qv = __ldg(query4 + (b * Q_ + q) * (D_ / 4) + lane);
        qv.x *= SCALE; qv.y *= SCALE; qv.z *= SCALE; qv.w *= SCALE;
        const float4* kp = key4 + ((size_t)(b * Q_ + q) * K_ + k1) * (D_ / 4);
        #pragma unroll 8
        for (int kk = 0; kk < CHUNK; kk++) {
            float4 kv = __ldcs(kp + kk * 32 + lane);
            float p = qv.x * kv.x + qv.y * kv.y + qv.z * kv.z + qv.w * kv.w;
            p += __shfl_xor_sync(0xffffffffu, p, 16);
            p += __shfl_xor_sync(0xffffffffu, p, 8);
            p += __shfl_xor_sync(0xffffffffu, p, 4);
            p += __shfl_xor_sync(0xffffffffu, p, 2);
            p += __shfl_xor_sync(0xffffffffu, p, 1);
            if (lane == 0) att[warp][1][q][kk] = p;
        }

        // ph3 for chunk 0, keys 2q and 2q+1 (independent of the above)
        #pragma unroll
        for (int qq = 0; qq < Q_; qq++) {
            float2 a2 = *reinterpret_cast<const float2*>(&att[warp][0][qq][2 * q]);
            acc[qq].x += a2.x * v0.x + a2.y * v1.x;
            acc[qq].y += a2.x * v0.y + a2.y * v1.y;
            acc[qq].z += a2.x * v0.z + a2.y * v1.z;
            acc[qq].w += a2.x * v0.w + a2.y * v1.w;
        }
    }
    __syncwarp();

    // ---- softmax over q for chunk 1 ----
    {
        float l[Q_];
        float mx = -1e30f;
        #pragma unroll
        for (int q = 0; q < Q_; q++) { l[q] = att[warp][1][q][lane]; mx = fmaxf(mx, l[q]); }
        float s = 0.0f;
        #pragma unroll
        for (int q = 0; q < Q_; q++) { l[q] = __expf(l[q] - mx); s += l[q]; }
        float inv = 1.0f / s;
        #pragma unroll
        for (int q = 0; q < Q_; q++) {
            float a = l[q] * inv;
            att[warp][1][q][lane] = a;
            __stcs(&attn_out[(size_t)(b * Q_ + q) * K_ + k1 + lane], a);
        }
    }
    __syncwarp();

    // ================= Phase C: ph3 for chunk 1 (tail) =================
    #pragma unroll 1
    for (int kk = 0; kk < CHUNK; kk += 4) {
        const float4* vp = value4 + ((size_t)b * K_ + k1 + kk) * (V_ / 4) + lane;
        float4 v0 = __ldcs(vp);
        float4 v1 = __ldcs(vp + 32);
        float4 v2 = __ldcs(vp + 64);
        float4 v3 = __ldcs(vp + 96);
        #pragma unroll
        for (int qq = 0; qq < Q_; qq++) {
            float4 a4 = *reinterpret_cast<const float4*>(&att[warp][1][qq][kk]);
            acc[qq].x += a4.x * v0.x + a4.y * v1.x + a4.z * v2.x + a4.w * v3.x;
            acc[qq].y += a4.x * v0.y + a4.y * v1.y + a4.z * v2.y + a4.w * v3.y;
            acc[qq].z += a4.x * v0.z + a4.y * v1.z + a4.z * v2.z + a4.w * v3.z;
            acc[qq].w += a4.x * v0.w + a4.y * v1.w + a4.z * v2.w + a4.w * v3.w;
        }
    }

    // ---- flush: one RED.v4 per q per lane ----
    float* o = out + (size_t)b * Q_ * V_ + lane * 4;
    #pragma unroll
    for (int q = 0; q < Q_; q++)
        red_add_v4(o + (size_t)q * V_, acc[q]);
}

extern "C" void kernel_launch(void* const* d_in, const int* in_sizes, int n_in,
                              void* d_out, int out_size)
{
    const float4* query = (const float4*)d_in[0];
    const float4* key   = (const float4*)d_in[1];
    const float4* value = (const float4*)d_in[2];

    float* out = (float*)d_out;
    float* attn;
    const int out_elems  = B_ * Q_ * V_;        // 65536
    const int attn_elems = B_ * Q_ * K_;        // 2097152

    if (out_size >= out_elems + attn_elems) {
        attn = out + out_elems;                 // (output, attn) concatenated
    } else {
        cudaGetSymbolAddress((void**)&attn, g_attn_scratch);
    }

    cudaMemsetAsync(d_out, 0, (size_t)out_elems * sizeof(float));

    inv_attn_kernel<<<GRID, THREADS>>>(query, key, value, out, attn);
}